// round 15
// baseline (speedup 1.0000x reference)
#include <cuda_runtime.h>
#include <cuda_bf16.h>

#define HIDDEN 256
#define HEADS 8
#define HEAD_DIM 32
#define NROWS 4096
#define NGRAPH 16
#define LN_EPS 1e-5f
#define SCALE 0.17677669529663687f  // 32^-0.5

typedef unsigned long long u64;

// ---------------- packed fp32x2 helpers (Blackwell FFMA2) ----------------
__device__ __forceinline__ u64 ffma2(u64 a, u64 b, u64 c) {
    u64 d; asm("fma.rn.f32x2 %0, %1, %2, %3;" : "=l"(d) : "l"(a), "l"(b), "l"(c)); return d;
}
__device__ __forceinline__ u64 fadd2(u64 a, u64 b) {
    u64 d; asm("add.rn.f32x2 %0, %1, %2;" : "=l"(d) : "l"(a), "l"(b)); return d;
}
__device__ __forceinline__ u64 fmul2(u64 a, u64 b) {
    u64 d; asm("mul.rn.f32x2 %0, %1, %2;" : "=l"(d) : "l"(a), "l"(b)); return d;
}
__device__ __forceinline__ u64 pack2(float lo, float hi) {
    u64 d; asm("mov.b64 %0, {%1, %2};" : "=l"(d) : "f"(lo), "f"(hi)); return d;
}
__device__ __forceinline__ void unpack2(u64 v, float& lo, float& hi) {
    asm("mov.b64 {%0, %1}, %2;" : "=f"(lo), "=f"(hi) : "l"(v));
}

// ---------------- scratch (no allocation allowed) ----------------
__device__ float g_h[NROWS * HIDDEN];
__device__ float g_q[NROWS * HIDDEN];
__device__ float g_k[NROWS * HIDDEN];
__device__ float g_v[NROWS * HIDDEN];
__device__ float g_att[NROWS * HIDDEN];

// ---------------- LayerNorm: one block per row ----------------
__global__ void ln_kernel(const float* __restrict__ x,
                          const float* __restrict__ gamma,
                          const float* __restrict__ beta,
                          float* __restrict__ h)
{
    int i = blockIdx.x;
    int t = threadIdx.x;          // 256 threads, one element each
    __shared__ float red1[8];
    __shared__ float red2[8];

    float val = x[i * HIDDEN + t];

    float s = val;
    #pragma unroll
    for (int o = 16; o > 0; o >>= 1) s += __shfl_xor_sync(0xffffffffu, s, o);
    if ((t & 31) == 0) red1[t >> 5] = s;
    __syncthreads();
    float mean = 0.f;
    #pragma unroll
    for (int q = 0; q < 8; q++) mean += red1[q];
    mean *= (1.0f / HIDDEN);

    float dv = val - mean;
    float s2 = dv * dv;
    #pragma unroll
    for (int o = 16; o > 0; o >>= 1) s2 += __shfl_xor_sync(0xffffffffu, s2, o);
    if ((t & 31) == 0) red2[t >> 5] = s2;
    __syncthreads();
    float var = 0.f;
    #pragma unroll
    for (int q = 0; q < 8; q++) var += red2[q];
    var *= (1.0f / HIDDEN);

    h[i * HIDDEN + t] = dv * rsqrtf(var + LN_EPS) * gamma[t] + beta[t];
}

// ---------------- Double-buffered f32x2 GEMM core ----------------
// A tile stored transposed AND duplicated as {a,a} 64-bit pairs, so the inner
// loop needs zero packing movs: A side = LDS of pre-packed pairs, B side =
// naturally-packed consecutive floats.
#define BM 64
#define BN 64
#define BK 16
#define TM 4
#define TN 4

__device__ __forceinline__ void gemm_tile_db(const float* __restrict__ A,
                                             const float* __restrict__ W,
                                             const float* __restrict__ bias,
                                             const float* __restrict__ residual,
                                             float* __restrict__ C,
                                             int bm, int bn)
{
    const int K = HIDDEN, N = HIDDEN;
    __shared__ u64   As2[2][BK][BM];   // transposed + duplicated {a,a}
    __shared__ float Bs[2][BK][BN];

    int tid = threadIdx.x;          // 256 threads
    int tx = tid & 15;
    int ty = tid >> 4;

    int arow  = tid >> 2;           // 0..63
    int acol4 = (tid & 3) * 4;      // 0,4,8,12
    int brow  = tid >> 4;           // 0..15
    int bcol4 = (tid & 15) * 4;

    u64 acc2[TM][TN / 2];
    #pragma unroll
    for (int i = 0; i < TM; i++)
        #pragma unroll
        for (int j = 0; j < TN / 2; j++) acc2[i][j] = 0ull;

    // preload tile 0
    float4 a = *(const float4*)&A[(bm + arow) * K + acol4];
    float4 b = *(const float4*)&W[brow * N + bn + bcol4];
    As2[0][acol4 + 0][arow] = pack2(a.x, a.x);
    As2[0][acol4 + 1][arow] = pack2(a.y, a.y);
    As2[0][acol4 + 2][arow] = pack2(a.z, a.z);
    As2[0][acol4 + 3][arow] = pack2(a.w, a.w);
    *(float4*)&Bs[0][brow][bcol4] = b;
    __syncthreads();

    int buf = 0;
    for (int k0 = 0; k0 < K; k0 += BK) {
        bool has_next = (k0 + BK < K);
        if (has_next) {
            a = *(const float4*)&A[(bm + arow) * K + k0 + BK + acol4];
            b = *(const float4*)&W[(k0 + BK + brow) * N + bn + bcol4];
        }

        #pragma unroll
        for (int kk = 0; kk < BK; kk++) {
            ulonglong2 ar01 = *(const ulonglong2*)&As2[buf][kk][ty * TM];
            ulonglong2 ar23 = *(const ulonglong2*)&As2[buf][kk][ty * TM + 2];
            ulonglong2 bb   = *(const ulonglong2*)&Bs[buf][kk][tx * TN];
            acc2[0][0] = ffma2(ar01.x, bb.x, acc2[0][0]);
            acc2[0][1] = ffma2(ar01.x, bb.y, acc2[0][1]);
            acc2[1][0] = ffma2(ar01.y, bb.x, acc2[1][0]);
            acc2[1][1] = ffma2(ar01.y, bb.y, acc2[1][1]);
            acc2[2][0] = ffma2(ar23.x, bb.x, acc2[2][0]);
            acc2[2][1] = ffma2(ar23.x, bb.y, acc2[2][1]);
            acc2[3][0] = ffma2(ar23.y, bb.x, acc2[3][0]);
            acc2[3][1] = ffma2(ar23.y, bb.y, acc2[3][1]);
        }

        if (has_next) {
            int nb = buf ^ 1;
            As2[nb][acol4 + 0][arow] = pack2(a.x, a.x);
            As2[nb][acol4 + 1][arow] = pack2(a.y, a.y);
            As2[nb][acol4 + 2][arow] = pack2(a.z, a.z);
            As2[nb][acol4 + 3][arow] = pack2(a.w, a.w);
            *(float4*)&Bs[nb][brow][bcol4] = b;
            __syncthreads();
            buf = nb;
        }
    }

    #pragma unroll
    for (int i = 0; i < TM; i++) {
        int row = bm + ty * TM + i;
        #pragma unroll
        for (int j = 0; j < TN / 2; j++) {
            int col = bn + tx * TN + j * 2;
            float lo, hi;
            unpack2(acc2[i][j], lo, hi);
            float v0 = lo + bias[col];
            float v1 = hi + bias[col + 1];
            if (residual) {
                v0 += residual[row * N + col];
                v1 += residual[row * N + col + 1];
            }
            C[row * N + col]     = v0;
            C[row * N + col + 1] = v1;
        }
    }
}

// Fused QKV GEMM: blockIdx.z selects {q,k,v}.
__global__ void __launch_bounds__(256) gemm_qkv(
    const float* __restrict__ A,
    const float* __restrict__ Wq, const float* __restrict__ bq, float* __restrict__ Cq,
    const float* __restrict__ Wk, const float* __restrict__ bk, float* __restrict__ Ck,
    const float* __restrict__ Wv, const float* __restrict__ bv, float* __restrict__ Cv)
{
    const float* W; const float* bias; float* C;
    if (blockIdx.z == 0)      { W = Wq; bias = bq; C = Cq; }
    else if (blockIdx.z == 1) { W = Wk; bias = bk; C = Ck; }
    else                      { W = Wv; bias = bv; C = Cv; }
    gemm_tile_db(A, W, bias, nullptr, C, blockIdx.y * BM, blockIdx.x * BN);
}

__global__ void __launch_bounds__(256) gemm_out(
    const float* __restrict__ A,
    const float* __restrict__ W,
    const float* __restrict__ bias,
    const float* __restrict__ residual,
    float* __restrict__ C)
{
    gemm_tile_db(A, W, bias, residual, C, blockIdx.y * BM, blockIdx.x * BN);
}

// ---------------- Block-diagonal attention (f32x2 inner math) ----------------
// grid (NGRAPH, HEADS, 2): 2 query-halves per (graph, head). 128 threads,
// thread = one query row. K/V staged in shared. Scores computed in chunks of
// KCH=8 per thread; softmax rescale amortized once per chunk.
#define CHUNK 128
#define KCH 8

__global__ void __launch_bounds__(128) attn_kernel(
    const float* __restrict__ q,
    const float* __restrict__ k,
    const float* __restrict__ v,
    const int* __restrict__ batch,
    float* __restrict__ out)
{
    __shared__ float sK[CHUNK][HEAD_DIM];
    __shared__ float sV[CHUNK][HEAD_DIM];
    __shared__ int sBounds[2];

    int g = blockIdx.x;      // graph id
    int h = blockIdx.y;      // head
    int half = blockIdx.z;   // query half
    int t = threadIdx.x;     // 0..127

    if (t == 0) {
        int lo = 0, hi = NROWS;
        while (lo < hi) { int mid = (lo + hi) >> 1; if (batch[mid] <  g) lo = mid + 1; else hi = mid; }
        sBounds[0] = lo;
        int lo2 = lo; hi = NROWS;
        while (lo2 < hi) { int mid = (lo2 + hi) >> 1; if (batch[mid] <= g) lo2 = mid + 1; else hi = mid; }
        sBounds[1] = lo2;
    }
    __syncthreads();
    int s0 = sBounds[0], e0 = sBounds[1];
    if (s0 >= e0) return;    // graph id absent

    int hbase = h * HEAD_DIM;

    for (int q0 = s0 + half * 128; q0 < e0; q0 += 256) {
        int qi = q0 + t;
        bool active = (qi < e0);

        u64 qv2[16];           // 16 packed pairs of scaled q
        if (active) {
            const float4* qp = (const float4*)(q + (size_t)qi * HIDDEN + hbase);
            #pragma unroll
            for (int i = 0; i < 8; i++) {
                float4 x4 = qp[i];
                qv2[i * 2]     = pack2(x4.x * SCALE, x4.y * SCALE);
                qv2[i * 2 + 1] = pack2(x4.z * SCALE, x4.w * SCALE);
            }
        }
        float m = -1e30f, l = 0.f;
        u64 acc2[16];
        #pragma unroll
        for (int i = 0; i < 16; i++) acc2[i] = 0ull;

        for (int c0 = s0; c0 < e0; c0 += CHUNK) {
            int cn = min(CHUNK, e0 - c0);
            __syncthreads();
            for (int idx = t; idx < cn * 8; idx += 128) {
                int row = idx >> 3, c4 = idx & 7;
                size_t goff = (size_t)(c0 + row) * HIDDEN + hbase + c4 * 4;
                ((float4*)sK[row])[c4] = *(const float4*)(k + goff);
                ((float4*)sV[row])[c4] = *(const float4*)(v + goff);
            }
            __syncthreads();

            if (active) {
                for (int j0 = 0; j0 < cn; j0 += KCH) {
                    // 1) scores for KCH keys into registers + chunk max
                    float sc[KCH];
                    float cmax = -3e38f;
                    #pragma unroll
                    for (int jj = 0; jj < KCH; jj++) {
                        int j = j0 + jj;
                        float s;
                        if (j < cn) {               // uniform branch
                            const ulonglong2* kr = (const ulonglong2*)sK[j];
                            u64 p0 = 0ull, p1 = 0ull, p2 = 0ull, p3 = 0ull;
                            #pragma unroll
                            for (int i = 0; i < 4; i++) {
                                ulonglong2 ka = kr[i * 2];
                                ulonglong2 kb = kr[i * 2 + 1];
                                p0 = ffma2(qv2[i * 4 + 0], ka.x, p0);
                                p1 = ffma2(qv2[i * 4 + 1], ka.y, p1);
                                p2 = ffma2(qv2[i * 4 + 2], kb.x, p2);
                                p3 = ffma2(qv2[i * 4 + 3], kb.y, p3);
                            }
                            u64 tsum = fadd2(fadd2(p0, p1), fadd2(p2, p3));
                            float lo, hi;
                            unpack2(tsum, lo, hi);
                            s = lo + hi;
                        } else {
                            s = -3e38f;             // padded -> exp() == 0
                        }
                        sc[jj] = s;
                        cmax = fmaxf(cmax, s);
                    }
                    // 2) rescale once per chunk (rare after warm-up)
                    if (cmax > m) {
                        float co = __expf(m - cmax);
                        l *= co;
                        u64 cc = pack2(co, co);
                        #pragma unroll
                        for (int i = 0; i < 16; i++) acc2[i] = fmul2(acc2[i], cc);
                        m = cmax;
                    }
                    // 3) exp + accumulate
                    #pragma unroll
                    for (int jj = 0; jj < KCH; jj++) {
                        float p = __expf(sc[jj] - m);
                        l += p;
                        u64 pp = pack2(p, p);
                        const ulonglong2* vr = (const ulonglong2*)sV[j0 + jj];
                        #pragma unroll
                        for (int i = 0; i < 8; i++) {
                            ulonglong2 v2 = vr[i];
                            acc2[i * 2]     = ffma2(pp, v2.x, acc2[i * 2]);
                            acc2[i * 2 + 1] = ffma2(pp, v2.y, acc2[i * 2 + 1]);
                        }
                    }
                }
            }
        }

        if (active) {
            float inv = 1.f / l;
            u64 iv = pack2(inv, inv);
            u64* op = (u64*)(out + (size_t)qi * HIDDEN + hbase);
            #pragma unroll
            for (int i = 0; i < 16; i++)
                op[i] = fmul2(acc2[i], iv);
        }
    }
}

// ---------------- launch ----------------
extern "C" void kernel_launch(void* const* d_in, const int* in_sizes, int n_in,
                              void* d_out, int out_size)
{
    const float* x     = (const float*)d_in[0];
    const int*   batch = (const int*)d_in[1];   // int32 (JAX x64 disabled)
    const float* Wq = (const float*)d_in[2];
    const float* bq = (const float*)d_in[3];
    const float* Wk = (const float*)d_in[4];
    const float* bk = (const float*)d_in[5];
    const float* Wv = (const float*)d_in[6];
    const float* bv = (const float*)d_in[7];
    const float* Wo = (const float*)d_in[8];
    const float* bo = (const float*)d_in[9];
    const float* gamma = (const float*)d_in[10];
    const float* beta  = (const float*)d_in[11];
    float* out = (float*)d_out;

    float *h_p, *q_p, *k_p, *v_p, *att_p;
    cudaGetSymbolAddress((void**)&h_p,  g_h);
    cudaGetSymbolAddress((void**)&q_p,  g_q);
    cudaGetSymbolAddress((void**)&k_p,  g_k);
    cudaGetSymbolAddress((void**)&v_p,  g_v);
    cudaGetSymbolAddress((void**)&att_p, g_att);

    ln_kernel<<<NROWS, 256>>>(x, gamma, beta, h_p);

    dim3 gqkv(HIDDEN / BN, NROWS / BM, 3);
    gemm_qkv<<<gqkv, 256>>>(h_p, Wq, bq, q_p, Wk, bk, k_p, Wv, bv, v_p);

    dim3 ga(NGRAPH, HEADS, 2);
    attn_kernel<<<ga, 128>>>(q_p, k_p, v_p, batch, att_p);

    dim3 gg(HIDDEN / BN, NROWS / BM);
    gemm_out<<<gg, 256>>>(att_p, Wo, bo, x, out);
}

// round 16
// speedup vs baseline: 1.4288x; 1.4288x over previous
#include <cuda_runtime.h>
#include <cuda_bf16.h>

#define HIDDEN 256
#define HEADS 8
#define HEAD_DIM 32
#define NROWS 4096
#define NGRAPH 16
#define LN_EPS 1e-5f
#define SCALE 0.17677669529663687f  // 32^-0.5

// ---------------- scratch (no allocation allowed) ----------------
__device__ float g_h[NROWS * HIDDEN];
__device__ float g_q[NROWS * HIDDEN];
__device__ float g_k[NROWS * HIDDEN];
__device__ float g_v[NROWS * HIDDEN];
__device__ float g_att[NROWS * HIDDEN];

// ---------------- LayerNorm: one block per row ----------------
__global__ void ln_kernel(const float* __restrict__ x,
                          const float* __restrict__ gamma,
                          const float* __restrict__ beta,
                          float* __restrict__ h)
{
    int i = blockIdx.x;
    int t = threadIdx.x;          // 256 threads, one element each
    __shared__ float red1[8];
    __shared__ float red2[8];

    float val = x[i * HIDDEN + t];

    float s = val;
    #pragma unroll
    for (int o = 16; o > 0; o >>= 1) s += __shfl_xor_sync(0xffffffffu, s, o);
    if ((t & 31) == 0) red1[t >> 5] = s;
    __syncthreads();
    float mean = 0.f;
    #pragma unroll
    for (int q = 0; q < 8; q++) mean += red1[q];
    mean *= (1.0f / HIDDEN);

    float dv = val - mean;
    float s2 = dv * dv;
    #pragma unroll
    for (int o = 16; o > 0; o >>= 1) s2 += __shfl_xor_sync(0xffffffffu, s2, o);
    if ((t & 31) == 0) red2[t >> 5] = s2;
    __syncthreads();
    float var = 0.f;
    #pragma unroll
    for (int q = 0; q < 8; q++) var += red2[q];
    var *= (1.0f / HIDDEN);

    h[i * HIDDEN + t] = dv * rsqrtf(var + LN_EPS) * gamma[t] + beta[t];
}

// ---------------- Double-buffered fp32 GEMM, 8x4 register tile ----------------
// BM=128, BN=64, BK=16, 256 threads. Smem bytes per lane-FMA = 1.5 (below the
// 2.0 crossbar/FMA balance point) -> FMA-bound, smem hides underneath.
#define BM 128
#define BN 64
#define BK 16
#define TM 8
#define TN 4

__device__ __forceinline__ void gemm_tile_db(const float* __restrict__ A,
                                             const float* __restrict__ W,
                                             const float* __restrict__ bias,
                                             const float* __restrict__ residual,
                                             float* __restrict__ C,
                                             int bm, int bn)
{
    const int K = HIDDEN, N = HIDDEN;
    __shared__ float As[2][BK][BM];   // transposed A tile
    __shared__ float Bs[2][BK][BN];

    int tid = threadIdx.x;          // 256 threads
    int tx = tid & 15;              // 16 col-groups * TN(4) = 64
    int ty = tid >> 4;              // 16 row-groups * TM(8) = 128

    // A tile: 128 rows x 16 cols = 512 float4 -> 2 per thread (rows r, r+64)
    int arow  = tid >> 2;           // 0..63
    int acol4 = (tid & 3) * 4;      // 0,4,8,12
    // B tile: 16 rows x 64 cols = 256 float4 -> 1 per thread
    int brow  = tid >> 4;           // 0..15
    int bcol4 = (tid & 15) * 4;

    float acc[TM][TN];
    #pragma unroll
    for (int i = 0; i < TM; i++)
        #pragma unroll
        for (int j = 0; j < TN; j++) acc[i][j] = 0.f;

    // preload tile 0
    float4 a0 = *(const float4*)&A[(bm + arow) * K + acol4];
    float4 a1 = *(const float4*)&A[(bm + arow + 64) * K + acol4];
    float4 b  = *(const float4*)&W[brow * N + bn + bcol4];
    #pragma unroll
    for (int c = 0; c < 4; c++) {
        As[0][acol4 + c][arow]      = (&a0.x)[c];
        As[0][acol4 + c][arow + 64] = (&a1.x)[c];
    }
    *(float4*)&Bs[0][brow][bcol4] = b;
    __syncthreads();

    int buf = 0;
    for (int k0 = 0; k0 < K; k0 += BK) {
        bool has_next = (k0 + BK < K);
        if (has_next) {
            a0 = *(const float4*)&A[(bm + arow) * K + k0 + BK + acol4];
            a1 = *(const float4*)&A[(bm + arow + 64) * K + k0 + BK + acol4];
            b  = *(const float4*)&W[(k0 + BK + brow) * N + bn + bcol4];
        }

        #pragma unroll
        for (int kk = 0; kk < BK; kk++) {
            float4 arA = *(const float4*)&As[buf][kk][ty * TM];
            float4 arB = *(const float4*)&As[buf][kk][ty * TM + 4];
            float4 br4 = *(const float4*)&Bs[buf][kk][tx * TN];
            const float ar[TM] = {arA.x, arA.y, arA.z, arA.w,
                                  arB.x, arB.y, arB.z, arB.w};
            const float br[TN] = {br4.x, br4.y, br4.z, br4.w};
            #pragma unroll
            for (int i = 0; i < TM; i++)
                #pragma unroll
                for (int j = 0; j < TN; j++)
                    acc[i][j] = fmaf(ar[i], br[j], acc[i][j]);
        }

        if (has_next) {
            int nb = buf ^ 1;
            #pragma unroll
            for (int c = 0; c < 4; c++) {
                As[nb][acol4 + c][arow]      = (&a0.x)[c];
                As[nb][acol4 + c][arow + 64] = (&a1.x)[c];
            }
            *(float4*)&Bs[nb][brow][bcol4] = b;
            __syncthreads();
            buf = nb;
        }
    }

    float4 b4 = *(const float4*)&bias[bn + tx * TN];
    #pragma unroll
    for (int i = 0; i < TM; i++) {
        int row = bm + ty * TM + i;
        int col = bn + tx * TN;
        float4 o;
        o.x = acc[i][0] + b4.x;
        o.y = acc[i][1] + b4.y;
        o.z = acc[i][2] + b4.z;
        o.w = acc[i][3] + b4.w;
        if (residual) {
            float4 r4 = *(const float4*)&residual[row * N + col];
            o.x += r4.x; o.y += r4.y; o.z += r4.z; o.w += r4.w;
        }
        *(float4*)&C[row * N + col] = o;
    }
}

// Fused QKV GEMM: blockIdx.z selects {q,k,v}.
__global__ void __launch_bounds__(256) gemm_qkv(
    const float* __restrict__ A,
    const float* __restrict__ Wq, const float* __restrict__ bq, float* __restrict__ Cq,
    const float* __restrict__ Wk, const float* __restrict__ bk, float* __restrict__ Ck,
    const float* __restrict__ Wv, const float* __restrict__ bv, float* __restrict__ Cv)
{
    const float* W; const float* bias; float* C;
    if (blockIdx.z == 0)      { W = Wq; bias = bq; C = Cq; }
    else if (blockIdx.z == 1) { W = Wk; bias = bk; C = Ck; }
    else                      { W = Wv; bias = bv; C = Cv; }
    gemm_tile_db(A, W, bias, nullptr, C, blockIdx.y * BM, blockIdx.x * BN);
}

__global__ void __launch_bounds__(256) gemm_out(
    const float* __restrict__ A,
    const float* __restrict__ W,
    const float* __restrict__ bias,
    const float* __restrict__ residual,
    float* __restrict__ C)
{
    gemm_tile_db(A, W, bias, residual, C, blockIdx.y * BM, blockIdx.x * BN);
}

// ---------------- Block-diagonal attention (R14 version, known good) ----------------
// grid (NGRAPH, HEADS, 2): 2 query-halves per (graph, head). 128 threads,
// thread = one query row. K/V staged in shared. Scores computed in chunks of
// KCH=8 per thread; softmax rescale amortized once per chunk.
#define CHUNK 128
#define KCH 8

__global__ void __launch_bounds__(128) attn_kernel(
    const float* __restrict__ q,
    const float* __restrict__ k,
    const float* __restrict__ v,
    const int* __restrict__ batch,
    float* __restrict__ out)
{
    __shared__ float sK[CHUNK][HEAD_DIM];
    __shared__ float sV[CHUNK][HEAD_DIM];
    __shared__ int sBounds[2];

    int g = blockIdx.x;      // graph id
    int h = blockIdx.y;      // head
    int half = blockIdx.z;   // query half
    int t = threadIdx.x;     // 0..127

    if (t == 0) {
        int lo = 0, hi = NROWS;
        while (lo < hi) { int mid = (lo + hi) >> 1; if (batch[mid] <  g) lo = mid + 1; else hi = mid; }
        sBounds[0] = lo;
        int lo2 = lo; hi = NROWS;
        while (lo2 < hi) { int mid = (lo2 + hi) >> 1; if (batch[mid] <= g) lo2 = mid + 1; else hi = mid; }
        sBounds[1] = lo2;
    }
    __syncthreads();
    int s0 = sBounds[0], e0 = sBounds[1];
    if (s0 >= e0) return;    // graph id absent

    int hbase = h * HEAD_DIM;

    for (int q0 = s0 + half * 128; q0 < e0; q0 += 256) {
        int qi = q0 + t;
        bool active = (qi < e0);

        float4 qv[8];
        if (active) {
            const float4* qp = (const float4*)(q + (size_t)qi * HIDDEN + hbase);
            #pragma unroll
            for (int i = 0; i < 8; i++) {
                float4 x4 = qp[i];
                x4.x *= SCALE; x4.y *= SCALE; x4.z *= SCALE; x4.w *= SCALE;
                qv[i] = x4;
            }
        }
        float m = -1e30f, l = 0.f;
        float4 acc[8];
        #pragma unroll
        for (int i = 0; i < 8; i++) acc[i] = make_float4(0.f, 0.f, 0.f, 0.f);

        for (int c0 = s0; c0 < e0; c0 += CHUNK) {
            int cn = min(CHUNK, e0 - c0);
            __syncthreads();
            for (int idx = t; idx < cn * 8; idx += 128) {
                int row = idx >> 3, c4 = idx & 7;
                size_t goff = (size_t)(c0 + row) * HIDDEN + hbase + c4 * 4;
                ((float4*)sK[row])[c4] = *(const float4*)(k + goff);
                ((float4*)sV[row])[c4] = *(const float4*)(v + goff);
            }
            __syncthreads();

            if (active) {
                for (int j0 = 0; j0 < cn; j0 += KCH) {
                    // 1) scores for KCH keys into registers + chunk max
                    float sc[KCH];
                    float cmax = -3e38f;
                    #pragma unroll
                    for (int jj = 0; jj < KCH; jj++) {
                        int j = j0 + jj;
                        float s;
                        if (j < cn) {               // uniform branch
                            const float4* kr = (const float4*)sK[j];
                            float p0 = 0.f, p1 = 0.f, p2 = 0.f, p3 = 0.f;
                            #pragma unroll
                            for (int i = 0; i < 8; i++) {
                                float4 k4 = kr[i];
                                p0 = fmaf(qv[i].x, k4.x, p0);
                                p1 = fmaf(qv[i].y, k4.y, p1);
                                p2 = fmaf(qv[i].z, k4.z, p2);
                                p3 = fmaf(qv[i].w, k4.w, p3);
                            }
                            s = (p0 + p1) + (p2 + p3);
                        } else {
                            s = -3e38f;             // padded -> exp() == 0
                        }
                        sc[jj] = s;
                        cmax = fmaxf(cmax, s);
                    }
                    // 2) rescale once per chunk (rare after warm-up)
                    if (cmax > m) {
                        float co = __expf(m - cmax);
                        l *= co;
                        #pragma unroll
                        for (int i = 0; i < 8; i++) {
                            acc[i].x *= co; acc[i].y *= co;
                            acc[i].z *= co; acc[i].w *= co;
                        }
                        m = cmax;
                    }
                    // 3) exp + accumulate
                    #pragma unroll
                    for (int jj = 0; jj < KCH; jj++) {
                        float p = __expf(sc[jj] - m);
                        l += p;
                        const float4* vr = (const float4*)sV[j0 + jj];
                        #pragma unroll
                        for (int i = 0; i < 8; i++) {
                            float4 v4 = vr[i];
                            acc[i].x = fmaf(p, v4.x, acc[i].x);
                            acc[i].y = fmaf(p, v4.y, acc[i].y);
                            acc[i].z = fmaf(p, v4.z, acc[i].z);
                            acc[i].w = fmaf(p, v4.w, acc[i].w);
                        }
                    }
                }
            }
        }

        if (active) {
            float inv = 1.f / l;
            float4* op = (float4*)(out + (size_t)qi * HIDDEN + hbase);
            #pragma unroll
            for (int i = 0; i < 8; i++) {
                float4 a4 = acc[i];
                a4.x *= inv; a4.y *= inv; a4.z *= inv; a4.w *= inv;
                op[i] = a4;
            }
        }
    }
}

// ---------------- launch ----------------
extern "C" void kernel_launch(void* const* d_in, const int* in_sizes, int n_in,
                              void* d_out, int out_size)
{
    const float* x     = (const float*)d_in[0];
    const int*   batch = (const int*)d_in[1];   // int32 (JAX x64 disabled)
    const float* Wq = (const float*)d_in[2];
    const float* bq = (const float*)d_in[3];
    const float* Wk = (const float*)d_in[4];
    const float* bk = (const float*)d_in[5];
    const float* Wv = (const float*)d_in[6];
    const float* bv = (const float*)d_in[7];
    const float* Wo = (const float*)d_in[8];
    const float* bo = (const float*)d_in[9];
    const float* gamma = (const float*)d_in[10];
    const float* beta  = (const float*)d_in[11];
    float* out = (float*)d_out;

    float *h_p, *q_p, *k_p, *v_p, *att_p;
    cudaGetSymbolAddress((void**)&h_p,  g_h);
    cudaGetSymbolAddress((void**)&q_p,  g_q);
    cudaGetSymbolAddress((void**)&k_p,  g_k);
    cudaGetSymbolAddress((void**)&v_p,  g_v);
    cudaGetSymbolAddress((void**)&att_p, g_att);

    ln_kernel<<<NROWS, 256>>>(x, gamma, beta, h_p);

    dim3 gqkv(HIDDEN / BN, NROWS / BM, 3);
    gemm_qkv<<<gqkv, 256>>>(h_p, Wq, bq, q_p, Wk, bk, k_p, Wv, bv, v_p);

    dim3 ga(NGRAPH, HEADS, 2);
    attn_kernel<<<ga, 128>>>(q_p, k_p, v_p, batch, att_p);

    dim3 gg(HIDDEN / BN, NROWS / BM);
    gemm_out<<<gg, 256>>>(att_p, Wo, bo, x, out);
}

// round 17
// speedup vs baseline: 1.6953x; 1.1866x over previous
#include <cuda_runtime.h>
#include <cuda_bf16.h>

#define HIDDEN 256
#define HEADS 8
#define HEAD_DIM 32
#define NROWS 4096
#define NGRAPH 16
#define LN_EPS 1e-5f
#define SCALE 0.17677669529663687f  // 32^-0.5

// ---------------- scratch (no allocation allowed) ----------------
__device__ float g_h[NROWS * HIDDEN];
__device__ float g_q[NROWS * HIDDEN];
__device__ float g_k[NROWS * HIDDEN];
__device__ float g_v[NROWS * HIDDEN];
__device__ float g_att[NROWS * HIDDEN];

// ---------------- tf32 helpers ----------------
__device__ __forceinline__ float cvt_tf32(float x) {
    unsigned r; asm("cvt.rna.tf32.f32 %0, %1;" : "=r"(r) : "f"(x));
    return __uint_as_float(r);
}
__device__ __forceinline__ void mma_tf32(float c[4], const unsigned a[4], const unsigned b[2]) {
    asm("mma.sync.aligned.m16n8k8.row.col.f32.tf32.tf32.f32 "
        "{%0,%1,%2,%3}, {%4,%5,%6,%7}, {%8,%9}, {%0,%1,%2,%3};"
        : "+f"(c[0]), "+f"(c[1]), "+f"(c[2]), "+f"(c[3])
        : "r"(a[0]), "r"(a[1]), "r"(a[2]), "r"(a[3]), "r"(b[0]), "r"(b[1]));
}

// ---------------- LayerNorm: one block per row ----------------
__global__ void ln_kernel(const float* __restrict__ x,
                          const float* __restrict__ gamma,
                          const float* __restrict__ beta,
                          float* __restrict__ h)
{
    int i = blockIdx.x;
    int t = threadIdx.x;          // 256 threads, one element each
    __shared__ float red1[8];
    __shared__ float red2[8];

    float val = x[i * HIDDEN + t];

    float s = val;
    #pragma unroll
    for (int o = 16; o > 0; o >>= 1) s += __shfl_xor_sync(0xffffffffu, s, o);
    if ((t & 31) == 0) red1[t >> 5] = s;
    __syncthreads();
    float mean = 0.f;
    #pragma unroll
    for (int q = 0; q < 8; q++) mean += red1[q];
    mean *= (1.0f / HIDDEN);

    float dv = val - mean;
    float s2 = dv * dv;
    #pragma unroll
    for (int o = 16; o > 0; o >>= 1) s2 += __shfl_xor_sync(0xffffffffu, s2, o);
    if ((t & 31) == 0) red2[t >> 5] = s2;
    __syncthreads();
    float var = 0.f;
    #pragma unroll
    for (int q = 0; q < 8; q++) var += red2[q];
    var *= (1.0f / HIDDEN);

    h[i * HIDDEN + t] = dv * rsqrtf(var + LN_EPS) * gamma[t] + beta[t];
}

// ---------------- tf32 tensor-core GEMM ----------------
// BM=128, BN=64, BK=16. 256 threads = 8 warps, warp tile 32x32
// (warp_m = wid&3 -> 4x32 rows, warp_n = wid>>2 -> 2x32 cols).
// Per warp: 2 m-frags x 4 n-frags of m16n8k8. Inputs tf32-rounded at
// smem-store time; accumulate fp32.
// Smem pads: A row stride 20 floats -> bank (20r+k)%32 bijective over warp;
// B row stride 68 -> bank (4k+n)%32 bijective. Conflict-free fragment loads.
#define BM 128
#define BN 64
#define BK 16
#define ASTRIDE 20
#define BSTRIDE 68

__device__ __forceinline__ void gemm_tile_mma(const float* __restrict__ A,
                                              const float* __restrict__ W,
                                              const float* __restrict__ bias,
                                              const float* __restrict__ residual,
                                              float* __restrict__ C,
                                              int bm, int bn)
{
    const int K = HIDDEN, N = HIDDEN;
    __shared__ float As[2][BM * ASTRIDE];   // [row][k], tf32-rounded
    __shared__ float Bs[2][BK * BSTRIDE];   // [k][n],  tf32-rounded

    int tid  = threadIdx.x;
    int lane = tid & 31;
    int wid  = tid >> 5;
    int wm   = wid & 3;          // warp row group (32 rows each)
    int wn   = wid >> 2;         // warp col group (32 cols each)

    // global->smem assignments
    // A tile: 128x16 = 512 float4, 2 per thread
    int ar0 = tid >> 2;                   // rows 0..63 (idx = tid)
    int ac0 = (tid & 3) * 4;
    int ar1 = (tid + 256) >> 2;           // rows 64..127
    // B tile: 16x64 = 256 float4, 1 per thread
    int br = tid >> 4;                    // 0..15
    int bc = (tid & 15) * 4;

    // fragment read offsets
    int fa_row = wm * 32 + (lane >> 2);   // a0 row; a1 +8; mi*16
    int fa_col = lane & 3;                // a0 k;  a2 +4
    int fb_n   = wn * 32 + (lane >> 2);   // b n;  ni*8
    int fb_k   = lane & 3;                // b0 k; b1 +4

    float acc[2][4][4];
    #pragma unroll
    for (int mi = 0; mi < 2; mi++)
        #pragma unroll
        for (int ni = 0; ni < 4; ni++)
            #pragma unroll
            for (int c = 0; c < 4; c++) acc[mi][ni][c] = 0.f;

    // preload chunk 0
    float4 a0 = *(const float4*)&A[(bm + ar0) * K + ac0];
    float4 a1 = *(const float4*)&A[(bm + ar1) * K + ac0];
    float4 b0 = *(const float4*)&W[br * N + bn + bc];
    {
        float* d0 = &As[0][ar0 * ASTRIDE + ac0];
        d0[0] = cvt_tf32(a0.x); d0[1] = cvt_tf32(a0.y);
        d0[2] = cvt_tf32(a0.z); d0[3] = cvt_tf32(a0.w);
        float* d1 = &As[0][ar1 * ASTRIDE + ac0];
        d1[0] = cvt_tf32(a1.x); d1[1] = cvt_tf32(a1.y);
        d1[2] = cvt_tf32(a1.z); d1[3] = cvt_tf32(a1.w);
        float* d2 = &Bs[0][br * BSTRIDE + bc];
        d2[0] = cvt_tf32(b0.x); d2[1] = cvt_tf32(b0.y);
        d2[2] = cvt_tf32(b0.z); d2[3] = cvt_tf32(b0.w);
    }
    __syncthreads();

    int buf = 0;
    for (int k0 = 0; k0 < K; k0 += BK) {
        bool has_next = (k0 + BK < K);
        if (has_next) {
            a0 = *(const float4*)&A[(bm + ar0) * K + k0 + BK + ac0];
            a1 = *(const float4*)&A[(bm + ar1) * K + k0 + BK + ac0];
            b0 = *(const float4*)&W[(k0 + BK + br) * N + bn + bc];
        }

        #pragma unroll
        for (int ks = 0; ks < 2; ks++) {
            int kb = ks * 8;
            unsigned af[2][4];
            #pragma unroll
            for (int mi = 0; mi < 2; mi++) {
                int r = (fa_row + mi * 16) * ASTRIDE + kb + fa_col;
                af[mi][0] = __float_as_uint(As[buf][r]);
                af[mi][1] = __float_as_uint(As[buf][r + 8 * ASTRIDE]);
                af[mi][2] = __float_as_uint(As[buf][r + 4]);
                af[mi][3] = __float_as_uint(As[buf][r + 8 * ASTRIDE + 4]);
            }
            unsigned bf[4][2];
            #pragma unroll
            for (int ni = 0; ni < 4; ni++) {
                int rb = (kb + fb_k) * BSTRIDE + fb_n + ni * 8;
                bf[ni][0] = __float_as_uint(Bs[buf][rb]);
                bf[ni][1] = __float_as_uint(Bs[buf][rb + 4 * BSTRIDE]);
            }
            #pragma unroll
            for (int mi = 0; mi < 2; mi++)
                #pragma unroll
                for (int ni = 0; ni < 4; ni++)
                    mma_tf32(acc[mi][ni], af[mi], bf[ni]);
        }

        if (has_next) {
            int nb = buf ^ 1;
            float* d0 = &As[nb][ar0 * ASTRIDE + ac0];
            d0[0] = cvt_tf32(a0.x); d0[1] = cvt_tf32(a0.y);
            d0[2] = cvt_tf32(a0.z); d0[3] = cvt_tf32(a0.w);
            float* d1 = &As[nb][ar1 * ASTRIDE + ac0];
            d1[0] = cvt_tf32(a1.x); d1[1] = cvt_tf32(a1.y);
            d1[2] = cvt_tf32(a1.z); d1[3] = cvt_tf32(a1.w);
            float* d2 = &Bs[nb][br * BSTRIDE + bc];
            d2[0] = cvt_tf32(b0.x); d2[1] = cvt_tf32(b0.y);
            d2[2] = cvt_tf32(b0.z); d2[3] = cvt_tf32(b0.w);
            __syncthreads();
            buf = nb;
        }
    }

    // epilogue: c0/c1 at (row, col), c2/c3 at (row+8, col); col = pair
    #pragma unroll
    for (int mi = 0; mi < 2; mi++) {
        int row0 = bm + wm * 32 + mi * 16 + (lane >> 2);
        #pragma unroll
        for (int ni = 0; ni < 4; ni++) {
            int col = bn + wn * 32 + ni * 8 + (lane & 3) * 2;
            float bx = bias[col], by = bias[col + 1];
            float v0 = acc[mi][ni][0] + bx;
            float v1 = acc[mi][ni][1] + by;
            float v2 = acc[mi][ni][2] + bx;
            float v3 = acc[mi][ni][3] + by;
            if (residual) {
                const float2 r0 = *(const float2*)&residual[row0 * N + col];
                const float2 r1 = *(const float2*)&residual[(row0 + 8) * N + col];
                v0 += r0.x; v1 += r0.y; v2 += r1.x; v3 += r1.y;
            }
            *(float2*)&C[row0 * N + col]       = make_float2(v0, v1);
            *(float2*)&C[(row0 + 8) * N + col] = make_float2(v2, v3);
        }
    }
}

// Fused QKV GEMM: blockIdx.z selects {q,k,v}.
__global__ void __launch_bounds__(256) gemm_qkv(
    const float* __restrict__ A,
    const float* __restrict__ Wq, const float* __restrict__ bq, float* __restrict__ Cq,
    const float* __restrict__ Wk, const float* __restrict__ bk, float* __restrict__ Ck,
    const float* __restrict__ Wv, const float* __restrict__ bv, float* __restrict__ Cv)
{
    const float* W; const float* bias; float* C;
    if (blockIdx.z == 0)      { W = Wq; bias = bq; C = Cq; }
    else if (blockIdx.z == 1) { W = Wk; bias = bk; C = Ck; }
    else                      { W = Wv; bias = bv; C = Cv; }
    gemm_tile_mma(A, W, bias, nullptr, C, blockIdx.y * BM, blockIdx.x * BN);
}

__global__ void __launch_bounds__(256) gemm_out(
    const float* __restrict__ A,
    const float* __restrict__ W,
    const float* __restrict__ bias,
    const float* __restrict__ residual,
    float* __restrict__ C)
{
    gemm_tile_mma(A, W, bias, residual, C, blockIdx.y * BM, blockIdx.x * BN);
}

// ---------------- Block-diagonal attention (R16 version, known good) ----------------
#define CHUNK 128
#define KCH 8

__global__ void __launch_bounds__(128) attn_kernel(
    const float* __restrict__ q,
    const float* __restrict__ k,
    const float* __restrict__ v,
    const int* __restrict__ batch,
    float* __restrict__ out)
{
    __shared__ float sK[CHUNK][HEAD_DIM];
    __shared__ float sV[CHUNK][HEAD_DIM];
    __shared__ int sBounds[2];

    int g = blockIdx.x;      // graph id
    int h = blockIdx.y;      // head
    int half = blockIdx.z;   // query half
    int t = threadIdx.x;     // 0..127

    if (t == 0) {
        int lo = 0, hi = NROWS;
        while (lo < hi) { int mid = (lo + hi) >> 1; if (batch[mid] <  g) lo = mid + 1; else hi = mid; }
        sBounds[0] = lo;
        int lo2 = lo; hi = NROWS;
        while (lo2 < hi) { int mid = (lo2 + hi) >> 1; if (batch[mid] <= g) lo2 = mid + 1; else hi = mid; }
        sBounds[1] = lo2;
    }
    __syncthreads();
    int s0 = sBounds[0], e0 = sBounds[1];
    if (s0 >= e0) return;    // graph id absent

    int hbase = h * HEAD_DIM;

    for (int q0 = s0 + half * 128; q0 < e0; q0 += 256) {
        int qi = q0 + t;
        bool active = (qi < e0);

        float4 qv[8];
        if (active) {
            const float4* qp = (const float4*)(q + (size_t)qi * HIDDEN + hbase);
            #pragma unroll
            for (int i = 0; i < 8; i++) {
                float4 x4 = qp[i];
                x4.x *= SCALE; x4.y *= SCALE; x4.z *= SCALE; x4.w *= SCALE;
                qv[i] = x4;
            }
        }
        float m = -1e30f, l = 0.f;
        float4 acc[8];
        #pragma unroll
        for (int i = 0; i < 8; i++) acc[i] = make_float4(0.f, 0.f, 0.f, 0.f);

        for (int c0 = s0; c0 < e0; c0 += CHUNK) {
            int cn = min(CHUNK, e0 - c0);
            __syncthreads();
            for (int idx = t; idx < cn * 8; idx += 128) {
                int row = idx >> 3, c4 = idx & 7;
                size_t goff = (size_t)(c0 + row) * HIDDEN + hbase + c4 * 4;
                ((float4*)sK[row])[c4] = *(const float4*)(k + goff);
                ((float4*)sV[row])[c4] = *(const float4*)(v + goff);
            }
            __syncthreads();

            if (active) {
                for (int j0 = 0; j0 < cn; j0 += KCH) {
                    float sc[KCH];
                    float cmax = -3e38f;
                    #pragma unroll
                    for (int jj = 0; jj < KCH; jj++) {
                        int j = j0 + jj;
                        float s;
                        if (j < cn) {               // uniform branch
                            const float4* kr = (const float4*)sK[j];
                            float p0 = 0.f, p1 = 0.f, p2 = 0.f, p3 = 0.f;
                            #pragma unroll
                            for (int i = 0; i < 8; i++) {
                                float4 k4 = kr[i];
                                p0 = fmaf(qv[i].x, k4.x, p0);
                                p1 = fmaf(qv[i].y, k4.y, p1);
                                p2 = fmaf(qv[i].z, k4.z, p2);
                                p3 = fmaf(qv[i].w, k4.w, p3);
                            }
                            s = (p0 + p1) + (p2 + p3);
                        } else {
                            s = -3e38f;             // padded -> exp() == 0
                        }
                        sc[jj] = s;
                        cmax = fmaxf(cmax, s);
                    }
                    if (cmax > m) {
                        float co = __expf(m - cmax);
                        l *= co;
                        #pragma unroll
                        for (int i = 0; i < 8; i++) {
                            acc[i].x *= co; acc[i].y *= co;
                            acc[i].z *= co; acc[i].w *= co;
                        }
                        m = cmax;
                    }
                    #pragma unroll
                    for (int jj = 0; jj < KCH; jj++) {
                        float p = __expf(sc[jj] - m);
                        l += p;
                        const float4* vr = (const float4*)sV[j0 + jj];
                        #pragma unroll
                        for (int i = 0; i < 8; i++) {
                            float4 v4 = vr[i];
                            acc[i].x = fmaf(p, v4.x, acc[i].x);
                            acc[i].y = fmaf(p, v4.y, acc[i].y);
                            acc[i].z = fmaf(p, v4.z, acc[i].z);
                            acc[i].w = fmaf(p, v4.w, acc[i].w);
                        }
                    }
                }
            }
        }

        if (active) {
            float inv = 1.f / l;
            float4* op = (float4*)(out + (size_t)qi * HIDDEN + hbase);
            #pragma unroll
            for (int i = 0; i < 8; i++) {
                float4 a4 = acc[i];
                a4.x *= inv; a4.y *= inv; a4.z *= inv; a4.w *= inv;
                op[i] = a4;
            }
        }
    }
}

// ---------------- launch ----------------
extern "C" void kernel_launch(void* const* d_in, const int* in_sizes, int n_in,
                              void* d_out, int out_size)
{
    const float* x     = (const float*)d_in[0];
    const int*   batch = (const int*)d_in[1];   // int32 (JAX x64 disabled)
    const float* Wq = (const float*)d_in[2];
    const float* bq = (const float*)d_in[3];
    const float* Wk = (const float*)d_in[4];
    const float* bk = (const float*)d_in[5];
    const float* Wv = (const float*)d_in[6];
    const float* bv = (const float*)d_in[7];
    const float* Wo = (const float*)d_in[8];
    const float* bo = (const float*)d_in[9];
    const float* gamma = (const float*)d_in[10];
    const float* beta  = (const float*)d_in[11];
    float* out = (float*)d_out;

    float *h_p, *q_p, *k_p, *v_p, *att_p;
    cudaGetSymbolAddress((void**)&h_p,  g_h);
    cudaGetSymbolAddress((void**)&q_p,  g_q);
    cudaGetSymbolAddress((void**)&k_p,  g_k);
    cudaGetSymbolAddress((void**)&v_p,  g_v);
    cudaGetSymbolAddress((void**)&att_p, g_att);

    ln_kernel<<<NROWS, 256>>>(x, gamma, beta, h_p);

    dim3 gqkv(HIDDEN / BN, NROWS / BM, 3);
    gemm_qkv<<<gqkv, 256>>>(h_p, Wq, bq, q_p, Wk, bk, k_p, Wv, bv, v_p);

    dim3 ga(NGRAPH, HEADS, 2);
    attn_kernel<<<ga, 128>>>(q_p, k_p, v_p, batch, att_p);

    dim3 gg(HIDDEN / BN, NROWS / BM);
    gemm_out<<<gg, 256>>>(att_p, Wo, bo, x, out);
}